// round 1
// baseline (speedup 1.0000x reference)
#include <cuda_runtime.h>
#include <math.h>

#define B_ 1024
#define S_ 254
#define C_ 2
#define H_ 1024
#define NSTEPS 50
#define DT 0.02f

// ---------------- scratch (static device globals; no allocations) ----------
__device__ float g_base0[B_ * H_];
__device__ float g_tvec[NSTEPS * H_];
__device__ float g_hA[B_ * H_];
__device__ float g_hB[B_ * H_];
__device__ float g_x[B_ * C_];

__device__ __forceinline__ float silu_f(float v) {
    return v / (1.0f + __expf(-v));
}

// ---------------- time-embedding contribution: tvec[step][j] ---------------
// tvec[i][j] = sum_k temb(t_i)[k] * W0[(256+k)*H + j]
__global__ void tvec_kernel(const float* __restrict__ W0, float* __restrict__ tvec) {
    __shared__ float temb[64];
    const int step = blockIdx.x;
    const int tid = threadIdx.x;
    const float t = (float)step * DT;
    if (tid < 64) {
        int k = tid & 31;
        float freq = expf(-9.210340371976184f * (float)k / 31.0f);  // ln(1e4)/31
        float ang = t * freq;
        temb[tid] = (tid < 32) ? sinf(ang) : cosf(ang);
    }
    __syncthreads();
    for (int j = tid; j < H_; j += blockDim.x) {
        float acc = 0.0f;
        #pragma unroll
        for (int k = 0; k < 64; k++)
            acc += temb[k] * W0[(size_t)(256 + k) * H_ + j];
        tvec[step * H_ + j] = acc;
    }
}

// ---------------- generic SGEMM: C = act(A[M,K] @ B[K,N] + bias) -----------
// BM=128, BN=64, BK=16, 256 threads, 8x4 micro-tile, double-buffered smem.
#define BM 128
#define BN 64
#define BKK 16

template <bool SILU, bool KGUARD>
__global__ __launch_bounds__(256) void sgemm_kernel(
    const float* __restrict__ A, int lda,
    const float* __restrict__ Bm, int ldb,
    const float* __restrict__ bias,
    float* __restrict__ Cm, int ldc, int K)
{
    __shared__ __align__(16) float As[2][BKK][BM + 4];
    __shared__ __align__(16) float Bs[2][BKK][BN];

    const int tid = threadIdx.x;
    const int tx = tid & 15;          // 0..15 -> n
    const int ty = tid >> 4;          // 0..15 -> m
    const int row0 = blockIdx.y * BM;
    const int col0 = blockIdx.x * BN;
    const int m0 = ty * 8;
    const int n0 = tx * 4;

    // global-load indexing
    const int arow = tid >> 2;        // 0..63  (+64 for second chunk)
    const int akq  = (tid & 3) * 4;   // k offset within tile: 0,4,8,12
    const int bk   = tid >> 4;        // 0..15
    const int bn   = (tid & 15) * 4;  // 0..60

    float acc[8][4];
    #pragma unroll
    for (int i = 0; i < 8; i++)
        #pragma unroll
        for (int j = 0; j < 4; j++) acc[i][j] = 0.0f;

    float4 ra[2], rb;

    auto gload = [&](int kt) {
        const int kbase = kt * BKK;
        #pragma unroll
        for (int i = 0; i < 2; i++) {
            int r = arow + i * 64;
            int k = kbase + akq;
            const float* p = A + (size_t)(row0 + r) * lda + k;
            if (KGUARD) {
                float4 v;
                v.x = (k + 0 < K) ? p[0] : 0.0f;
                v.y = (k + 1 < K) ? p[1] : 0.0f;
                v.z = (k + 2 < K) ? p[2] : 0.0f;
                v.w = (k + 3 < K) ? p[3] : 0.0f;
                ra[i] = v;
            } else {
                ra[i] = *reinterpret_cast<const float4*>(p);
            }
        }
        {
            int k = kbase + bk;
            const float* p = Bm + (size_t)k * ldb + col0 + bn;
            if (KGUARD) {
                float4 v = make_float4(0.f, 0.f, 0.f, 0.f);
                if (k < K) v = *reinterpret_cast<const float4*>(p);
                rb = v;
            } else {
                rb = *reinterpret_cast<const float4*>(p);
            }
        }
    };

    auto sstore = [&](int buf) {
        #pragma unroll
        for (int i = 0; i < 2; i++) {
            int r = arow + i * 64;
            As[buf][akq + 0][r] = ra[i].x;
            As[buf][akq + 1][r] = ra[i].y;
            As[buf][akq + 2][r] = ra[i].z;
            As[buf][akq + 3][r] = ra[i].w;
        }
        *reinterpret_cast<float4*>(&Bs[buf][bk][bn]) = rb;
    };

    const int ktiles = (K + BKK - 1) / BKK;

    gload(0);
    sstore(0);
    __syncthreads();

    for (int kt = 0; kt < ktiles; kt++) {
        const int buf = kt & 1;
        if (kt + 1 < ktiles) gload(kt + 1);

        #pragma unroll
        for (int kk = 0; kk < BKK; kk++) {
            float a[8], bv[4];
            #pragma unroll
            for (int i = 0; i < 8; i++) a[i] = As[buf][kk][m0 + i];
            #pragma unroll
            for (int j = 0; j < 4; j++) bv[j] = Bs[buf][kk][n0 + j];
            #pragma unroll
            for (int i = 0; i < 8; i++)
                #pragma unroll
                for (int j = 0; j < 4; j++)
                    acc[i][j] = fmaf(a[i], bv[j], acc[i][j]);
        }

        if (kt + 1 < ktiles) sstore(buf ^ 1);
        __syncthreads();
    }

    // epilogue: bias + optional SiLU, vectorized stores
    float bb[4];
    #pragma unroll
    for (int j = 0; j < 4; j++) bb[j] = bias[col0 + n0 + j];

    #pragma unroll
    for (int i = 0; i < 8; i++) {
        const int m = row0 + m0 + i;
        float4 o;
        float v0 = acc[i][0] + bb[0];
        float v1 = acc[i][1] + bb[1];
        float v2 = acc[i][2] + bb[2];
        float v3 = acc[i][3] + bb[3];
        if (SILU) {
            v0 = silu_f(v0); v1 = silu_f(v1); v2 = silu_f(v2); v3 = silu_f(v3);
        }
        o.x = v0; o.y = v1; o.z = v2; o.w = v3;
        *reinterpret_cast<float4*>(Cm + (size_t)m * ldc + col0 + n0) = o;
    }
}

// ---------------- layer-0 fused activation ---------------------------------
// h[b][j] = silu(base0[b][j] + tvec_step[j] + x[b,0]*W0row254[j] + x[b,1]*W0row255[j])
__global__ __launch_bounds__(256) void layer0_act(
    const float* __restrict__ base0, const float* __restrict__ tvec_step,
    const float* __restrict__ w254, const float* __restrict__ w255,
    const float* __restrict__ x, float* __restrict__ h)
{
    const int idx = blockIdx.x * blockDim.x + threadIdx.x;  // < B_*H_
    const int b = idx >> 10;
    const int j = idx & 1023;
    float v = base0[idx] + tvec_step[j] + x[2 * b] * w254[j] + x[2 * b + 1] * w255[j];
    h[idx] = silu_f(v);
}

// ---------------- output head + Euler update -------------------------------
// v[b][c] = h[b] . W4[:,c] + b4[c];  x[b][c] += DT * v[b][c]
__global__ __launch_bounds__(128) void out_euler(
    const float* __restrict__ h, const float* __restrict__ W4,
    const float* __restrict__ b4, float* __restrict__ x)
{
    const int b = blockIdx.x;
    const int tid = threadIdx.x;
    const float* hr = h + (size_t)b * H_;
    float s0 = 0.0f, s1 = 0.0f;
    for (int j = tid; j < H_; j += 128) {
        float hv = hr[j];
        float2 w = reinterpret_cast<const float2*>(W4)[j];
        s0 = fmaf(hv, w.x, s0);
        s1 = fmaf(hv, w.y, s1);
    }
    #pragma unroll
    for (int o = 16; o > 0; o >>= 1) {
        s0 += __shfl_down_sync(0xffffffffu, s0, o);
        s1 += __shfl_down_sync(0xffffffffu, s1, o);
    }
    __shared__ float r0[4], r1[4];
    const int w = tid >> 5, l = tid & 31;
    if (l == 0) { r0[w] = s0; r1[w] = s1; }
    __syncthreads();
    if (tid == 0) {
        float t0 = r0[0] + r0[1] + r0[2] + r0[3] + b4[0];
        float t1 = r1[0] + r1[1] + r1[2] + r1[3] + b4[1];
        x[2 * b]     += DT * t0;
        x[2 * b + 1] += DT * t1;
    }
}

__global__ void copy_out_kernel(const float* __restrict__ src, float* __restrict__ dst, int n) {
    int i = blockIdx.x * blockDim.x + threadIdx.x;
    if (i < n) dst[i] = src[i];
}

// ---------------- launch ----------------------------------------------------
extern "C" void kernel_launch(void* const* d_in, const int* in_sizes, int n_in,
                              void* d_out, int out_size)
{
    const float* state = (const float*)d_in[0];
    const float* x0    = (const float*)d_in[1];
    const float* W0    = (const float*)d_in[2];
    const float* b0    = (const float*)d_in[3];
    const float* W1    = (const float*)d_in[4];
    const float* b1    = (const float*)d_in[5];
    const float* W2    = (const float*)d_in[6];
    const float* b2    = (const float*)d_in[7];
    const float* W3    = (const float*)d_in[8];
    const float* b3    = (const float*)d_in[9];
    const float* W4    = (const float*)d_in[10];
    const float* b4    = (const float*)d_in[11];
    float* out = (float*)d_out;

    float *base0p, *tvecp, *hAp, *hBp, *xp;
    cudaGetSymbolAddress((void**)&base0p, g_base0);
    cudaGetSymbolAddress((void**)&tvecp,  g_tvec);
    cudaGetSymbolAddress((void**)&hAp,    g_hA);
    cudaGetSymbolAddress((void**)&hBp,    g_hB);
    cudaGetSymbolAddress((void**)&xp,     g_x);

    // x <- x0
    cudaMemcpyAsync(xp, x0, B_ * C_ * sizeof(float), cudaMemcpyDeviceToDevice);

    // precompute time-embedding contributions for all 50 steps
    tvec_kernel<<<NSTEPS, 256>>>(W0, tvecp);

    dim3 grid(H_ / BN, B_ / BM);  // (16, 8) = 128 CTAs

    // base0 = state @ W0[0:254] + b0   (K=254, unaligned A rows -> guarded path)
    sgemm_kernel<false, true><<<grid, 256>>>(state, S_, W0, H_, b0, base0p, H_, S_);

    for (int i = 0; i < NSTEPS; i++) {
        layer0_act<<<(B_ * H_) / 256, 256>>>(base0p, tvecp + i * H_,
                                             W0 + (size_t)254 * H_,
                                             W0 + (size_t)255 * H_, xp, hAp);
        sgemm_kernel<true, false><<<grid, 256>>>(hAp, H_, W1, H_, b1, hBp, H_, H_);
        sgemm_kernel<true, false><<<grid, 256>>>(hBp, H_, W2, H_, b2, hAp, H_, H_);
        sgemm_kernel<true, false><<<grid, 256>>>(hAp, H_, W3, H_, b3, hBp, H_, H_);
        out_euler<<<B_, 128>>>(hBp, W4, b4, xp);
    }

    copy_out_kernel<<<(B_ * C_ + 255) / 256, 256>>>(xp, out, B_ * C_);
}

// round 3
// speedup vs baseline: 2.1003x; 2.1003x over previous
#include <cuda_runtime.h>
#include <cuda_bf16.h>
#include <math.h>
#include <stdint.h>

#define B_ 1024
#define S_ 254
#define C_ 2
#define H_ 1024
#define NSTEPS 50
#define DT 0.02f

// ===================== helpers =============================================
__device__ __forceinline__ uint32_t smem_to_u32(const void* p) {
    uint32_t a;
    asm("{ .reg .u64 t; cvta.to.shared.u64 t, %1; cvt.u32.u64 %0, t; }" : "=r"(a) : "l"(p));
    return a;
}
#define CP_ASYNC16(dst, src) \
    asm volatile("cp.async.cg.shared.global [%0], [%1], 16;" :: "r"(dst), "l"(src) : "memory")
#define CP_COMMIT() asm volatile("cp.async.commit_group;" ::: "memory")
#define CP_WAIT1() asm volatile("cp.async.wait_group 1;" ::: "memory")

__device__ __forceinline__ void ldsm4(uint32_t* r, uint32_t addr) {
    asm volatile("ldmatrix.sync.aligned.m8n8.x4.shared.b16 {%0,%1,%2,%3}, [%4];"
        : "=r"(r[0]), "=r"(r[1]), "=r"(r[2]), "=r"(r[3]) : "r"(addr));
}
__device__ __forceinline__ void mma16816(float* c, const uint32_t* a, const uint32_t* b) {
    asm volatile("mma.sync.aligned.m16n8k16.row.col.f32.bf16.bf16.f32 "
        "{%0,%1,%2,%3}, {%4,%5,%6,%7}, {%8,%9}, {%0,%1,%2,%3};"
        : "+f"(c[0]), "+f"(c[1]), "+f"(c[2]), "+f"(c[3])
        : "r"(a[0]), "r"(a[1]), "r"(a[2]), "r"(a[3]), "r"(b[0]), "r"(b[1]));
}

__device__ __forceinline__ float silu_f(float v) { return v / (1.0f + __expf(-v)); }

__device__ __forceinline__ void split_pair(float v0, float v1, uint32_t& hi, uint32_t& lo) {
    __nv_bfloat16 h0 = __float2bfloat16(v0);
    __nv_bfloat16 h1 = __float2bfloat16(v1);
    __nv_bfloat16 l0 = __float2bfloat16(v0 - __bfloat162float(h0));
    __nv_bfloat16 l1 = __float2bfloat16(v1 - __bfloat162float(h1));
    hi = ((uint32_t)__bfloat16_as_ushort(h1) << 16) | (uint32_t)__bfloat16_as_ushort(h0);
    lo = ((uint32_t)__bfloat16_as_ushort(l1) << 16) | (uint32_t)__bfloat16_as_ushort(l0);
}

// ===================== scratch (device globals, no allocs) ==================
__device__ float g_base0[B_ * H_];
__device__ float g_tvec[NSTEPS * H_];
__device__ float g_x[B_ * C_];
__device__ __nv_bfloat16 g_actA_hi[B_ * H_];
__device__ __nv_bfloat16 g_actA_lo[B_ * H_];
__device__ __nv_bfloat16 g_actB_hi[B_ * H_];
__device__ __nv_bfloat16 g_actB_lo[B_ * H_];
__device__ __nv_bfloat16 g_w_hi[3][H_ * H_];  // [N,K] transposed
__device__ __nv_bfloat16 g_w_lo[3][H_ * H_];

// ===================== weight transpose + bf16 split ========================
__global__ void wsplit_kernel(const float* __restrict__ W,
                              __nv_bfloat16* __restrict__ hi,
                              __nv_bfloat16* __restrict__ lo) {
    __shared__ float t[32][33];
    const int k0 = blockIdx.y * 32, n0 = blockIdx.x * 32;
    const int tx = threadIdx.x, ty = threadIdx.y;
    for (int i = ty; i < 32; i += 8)
        t[i][tx] = W[(size_t)(k0 + i) * H_ + n0 + tx];
    __syncthreads();
    for (int i = ty; i < 32; i += 8) {
        float v = t[tx][i];  // W[k0+tx][n0+i]
        size_t o = (size_t)(n0 + i) * H_ + k0 + tx;
        __nv_bfloat16 h = __float2bfloat16(v);
        hi[o] = h;
        lo[o] = __float2bfloat16(v - __bfloat162float(h));
    }
}

// ===================== time-embedding contribution ==========================
__global__ void tvec_kernel(const float* __restrict__ W0, float* __restrict__ tvec) {
    __shared__ float temb[64];
    const int step = blockIdx.x;
    const int tid = threadIdx.x;
    const float t = (float)step * DT;
    if (tid < 64) {
        int k = tid & 31;
        float freq = expf(-9.210340371976184f * (float)k / 31.0f);
        float ang = t * freq;
        temb[tid] = (tid < 32) ? sinf(ang) : cosf(ang);
    }
    __syncthreads();
    for (int j = tid; j < H_; j += blockDim.x) {
        float acc = 0.0f;
        #pragma unroll
        for (int k = 0; k < 64; k++)
            acc += temb[k] * W0[(size_t)(256 + k) * H_ + j];
        tvec[step * H_ + j] = acc;
    }
}

// ===================== fp32 SGEMM for base0 (K=254, one-time) ===============
#define BM 128
#define BN 64
#define BKK 16
__global__ __launch_bounds__(256) void sgemm_kernel(
    const float* __restrict__ A, int lda,
    const float* __restrict__ Bm, int ldb,
    const float* __restrict__ bias,
    float* __restrict__ Cm, int ldc, int K)
{
    __shared__ __align__(16) float As[2][BKK][BM + 4];
    __shared__ __align__(16) float Bs[2][BKK][BN];
    const int tid = threadIdx.x;
    const int tx = tid & 15, ty = tid >> 4;
    const int row0 = blockIdx.y * BM, col0 = blockIdx.x * BN;
    const int m0 = ty * 8, n0 = tx * 4;
    const int arow = tid >> 2, akq = (tid & 3) * 4;
    const int bk = tid >> 4, bn = (tid & 15) * 4;

    float acc[8][4];
    #pragma unroll
    for (int i = 0; i < 8; i++)
        #pragma unroll
        for (int j = 0; j < 4; j++) acc[i][j] = 0.0f;
    float4 ra[2], rb;

    auto gload = [&](int kt) {
        const int kbase = kt * BKK;
        #pragma unroll
        for (int i = 0; i < 2; i++) {
            int r = arow + i * 64, k = kbase + akq;
            const float* p = A + (size_t)(row0 + r) * lda + k;
            float4 v;
            v.x = (k + 0 < K) ? p[0] : 0.0f;
            v.y = (k + 1 < K) ? p[1] : 0.0f;
            v.z = (k + 2 < K) ? p[2] : 0.0f;
            v.w = (k + 3 < K) ? p[3] : 0.0f;
            ra[i] = v;
        }
        int k = kbase + bk;
        const float* p = Bm + (size_t)k * ldb + col0 + bn;
        rb = (k < K) ? *reinterpret_cast<const float4*>(p) : make_float4(0, 0, 0, 0);
    };
    auto sstore = [&](int buf) {
        #pragma unroll
        for (int i = 0; i < 2; i++) {
            int r = arow + i * 64;
            As[buf][akq + 0][r] = ra[i].x;
            As[buf][akq + 1][r] = ra[i].y;
            As[buf][akq + 2][r] = ra[i].z;
            As[buf][akq + 3][r] = ra[i].w;
        }
        *reinterpret_cast<float4*>(&Bs[buf][bk][bn]) = rb;
    };

    const int ktiles = (K + BKK - 1) / BKK;
    gload(0); sstore(0); __syncthreads();
    for (int kt = 0; kt < ktiles; kt++) {
        const int buf = kt & 1;
        if (kt + 1 < ktiles) gload(kt + 1);
        #pragma unroll
        for (int kk = 0; kk < BKK; kk++) {
            float a[8], bv[4];
            #pragma unroll
            for (int i = 0; i < 8; i++) a[i] = As[buf][kk][m0 + i];
            #pragma unroll
            for (int j = 0; j < 4; j++) bv[j] = Bs[buf][kk][n0 + j];
            #pragma unroll
            for (int i = 0; i < 8; i++)
                #pragma unroll
                for (int j = 0; j < 4; j++)
                    acc[i][j] = fmaf(a[i], bv[j], acc[i][j]);
        }
        if (kt + 1 < ktiles) sstore(buf ^ 1);
        __syncthreads();
    }
    float bb[4];
    #pragma unroll
    for (int j = 0; j < 4; j++) bb[j] = bias[col0 + n0 + j];
    #pragma unroll
    for (int i = 0; i < 8; i++) {
        const int m = row0 + m0 + i;
        float4 o;
        o.x = acc[i][0] + bb[0]; o.y = acc[i][1] + bb[1];
        o.z = acc[i][2] + bb[2]; o.w = acc[i][3] + bb[3];
        *reinterpret_cast<float4*>(Cm + (size_t)m * ldc + col0 + n0) = o;
    }
}

// ===================== HMMA split-bf16 GEMM =================================
// C[M=1024,N=1024] = silu(Ahi*Whi^T + Ahi*Wlo^T + Alo*Whi^T + bias), split out.
// A: [M,K] bf16 hi/lo; W: [N,K] bf16 hi/lo.
// BM=128, BN=64, BK=32, 3-stage cp.async, 256 threads (4x2 warps, 32x32/warp).
#define GBM 128
#define GBN 64
#define GBK 32
#define GSTAGES 3
#define OFF_AHI 0
#define OFF_ALO 8192
#define OFF_BHI 16384
#define OFF_BLO 20480
#define STAGE_BYTES 24576
#define GSMEM_TOTAL (GSTAGES * STAGE_BYTES)

// swizzled byte offset inside one matrix region: 64B rows, 4x16B chunks
__device__ __forceinline__ uint32_t soff(int r, int ch) {
    return (uint32_t)(r * 64 + (((ch ^ (r >> 1)) & 3) << 4));
}

__global__ __launch_bounds__(256) void gemm_hmma(
    const __nv_bfloat16* __restrict__ Ahi, const __nv_bfloat16* __restrict__ Alo,
    const __nv_bfloat16* __restrict__ Whi, const __nv_bfloat16* __restrict__ Wlo,
    const float* __restrict__ bias,
    __nv_bfloat16* __restrict__ outHi, __nv_bfloat16* __restrict__ outLo)
{
    extern __shared__ __align__(1024) char gs[];
    const uint32_t sbase = smem_to_u32(gs);
    const int tid = threadIdx.x;
    const int row0 = blockIdx.y * GBM;
    const int col0 = blockIdx.x * GBN;

    auto load_stage = [&](int kt) {
        const uint32_t sb = sbase + (uint32_t)(kt % GSTAGES) * STAGE_BYTES;
        const int kb = kt * GBK;
        #pragma unroll
        for (int i = 0; i < 2; i++) {
            int c = tid + i * 256;
            int r = c >> 2, ch = c & 3;
            uint32_t sw = soff(r, ch);
            CP_ASYNC16(sb + OFF_AHI + sw, Ahi + (size_t)(row0 + r) * H_ + kb + ch * 8);
            CP_ASYNC16(sb + OFF_ALO + sw, Alo + (size_t)(row0 + r) * H_ + kb + ch * 8);
        }
        {
            int r = tid >> 2, ch = tid & 3;
            uint32_t sw = soff(r, ch);
            CP_ASYNC16(sb + OFF_BHI + sw, Whi + (size_t)(col0 + r) * H_ + kb + ch * 8);
            CP_ASYNC16(sb + OFF_BLO + sw, Wlo + (size_t)(col0 + r) * H_ + kb + ch * 8);
        }
    };

    const int lane = tid & 31;
    const int wid = tid >> 5;
    const int wm = wid & 3;   // 0..3 (M)
    const int wn = wid >> 2;  // 0..1 (N)

    float acc[2][4][4];
    #pragma unroll
    for (int mi = 0; mi < 2; mi++)
        #pragma unroll
        for (int ni = 0; ni < 4; ni++)
            #pragma unroll
            for (int q = 0; q < 4; q++) acc[mi][ni][q] = 0.0f;

    // lane-constant address components
    const int a_r = wm * 32 + (lane & 15);                      // + mi*16
    const int a_half = lane >> 4;                               // k-chunk half
    const int b_r = wn * 32 + (lane & 7) + ((lane >> 4) << 3);  // + nt*16
    const int b_half = (lane >> 3) & 1;

    load_stage(0); CP_COMMIT();
    load_stage(1); CP_COMMIT();

    const int NKT = H_ / GBK;  // 32
    for (int kt = 0; kt < NKT; kt++) {
        CP_WAIT1();
        __syncthreads();
        if (kt + 2 < NKT) load_stage(kt + 2);
        CP_COMMIT();

        const uint32_t sb = sbase + (uint32_t)(kt % GSTAGES) * STAGE_BYTES;
        #pragma unroll
        for (int ks = 0; ks < 2; ks++) {
            uint32_t ah[2][4], al[2][4];
            #pragma unroll
            for (int mi = 0; mi < 2; mi++) {
                int r = a_r + mi * 16;
                int ch = ks * 2 + a_half;
                uint32_t off = soff(r, ch);
                ldsm4(ah[mi], sb + OFF_AHI + off);
                ldsm4(al[mi], sb + OFF_ALO + off);
            }
            uint32_t bh[2][4], bl[2][4];
            #pragma unroll
            for (int nt = 0; nt < 2; nt++) {
                int r = b_r + nt * 16;
                int ch = ks * 2 + b_half;
                uint32_t off = soff(r, ch);
                ldsm4(bh[nt], sb + OFF_BHI + off);
                ldsm4(bl[nt], sb + OFF_BLO + off);
            }
            #pragma unroll
            for (int mi = 0; mi < 2; mi++)
                #pragma unroll
                for (int ni = 0; ni < 4; ni++) {
                    const uint32_t* BH = &bh[ni >> 1][(ni & 1) * 2];
                    const uint32_t* BL = &bl[ni >> 1][(ni & 1) * 2];
                    mma16816(acc[mi][ni], ah[mi], BH);
                    mma16816(acc[mi][ni], ah[mi], BL);
                    mma16816(acc[mi][ni], al[mi], BH);
                }
        }
    }

    // epilogue: bias + silu + bf16 split, direct gmem stores
    #pragma unroll
    for (int mi = 0; mi < 2; mi++) {
        const int r0g = row0 + wm * 32 + mi * 16 + (lane >> 2);
        #pragma unroll
        for (int ni = 0; ni < 4; ni++) {
            const int cg = col0 + wn * 32 + ni * 8 + (lane & 3) * 2;
            float2 bb = *reinterpret_cast<const float2*>(bias + cg);
            float v00 = silu_f(acc[mi][ni][0] + bb.x);
            float v01 = silu_f(acc[mi][ni][1] + bb.y);
            float v10 = silu_f(acc[mi][ni][2] + bb.x);
            float v11 = silu_f(acc[mi][ni][3] + bb.y);
            uint32_t h0, l0, h1, l1;
            split_pair(v00, v01, h0, l0);
            split_pair(v10, v11, h1, l1);
            *reinterpret_cast<uint32_t*>(outHi + (size_t)r0g * H_ + cg) = h0;
            *reinterpret_cast<uint32_t*>(outLo + (size_t)r0g * H_ + cg) = l0;
            *reinterpret_cast<uint32_t*>(outHi + (size_t)(r0g + 8) * H_ + cg) = h1;
            *reinterpret_cast<uint32_t*>(outLo + (size_t)(r0g + 8) * H_ + cg) = l1;
        }
    }
}

// ===================== layer-0 fused activation (splits output) =============
__global__ __launch_bounds__(256) void layer0_act(
    const float* __restrict__ base0, const float* __restrict__ tvec_step,
    const float* __restrict__ w254, const float* __restrict__ w255,
    const float* __restrict__ x,
    __nv_bfloat16* __restrict__ hi, __nv_bfloat16* __restrict__ lo)
{
    const int idx = blockIdx.x * blockDim.x + threadIdx.x;
    const int b = idx >> 10;
    const int j = idx & 1023;
    float v = base0[idx] + tvec_step[j] + x[2 * b] * w254[j] + x[2 * b + 1] * w255[j];
    float hv = silu_f(v);
    __nv_bfloat16 h = __float2bfloat16(hv);
    hi[idx] = h;
    lo[idx] = __float2bfloat16(hv - __bfloat162float(h));
}

// ===================== output head + Euler update ===========================
__global__ __launch_bounds__(128) void out_euler(
    const __nv_bfloat16* __restrict__ hHi, const __nv_bfloat16* __restrict__ hLo,
    const float* __restrict__ W4, const float* __restrict__ b4, float* __restrict__ x)
{
    const int b = blockIdx.x;
    const int tid = threadIdx.x;
    const __nv_bfloat16* ph = hHi + (size_t)b * H_;
    const __nv_bfloat16* pl = hLo + (size_t)b * H_;
    float s0 = 0.0f, s1 = 0.0f;
    for (int j = tid; j < H_; j += 128) {
        float hv = __bfloat162float(ph[j]) + __bfloat162float(pl[j]);
        float2 w = reinterpret_cast<const float2*>(W4)[j];
        s0 = fmaf(hv, w.x, s0);
        s1 = fmaf(hv, w.y, s1);
    }
    #pragma unroll
    for (int o = 16; o > 0; o >>= 1) {
        s0 += __shfl_down_sync(0xffffffffu, s0, o);
        s1 += __shfl_down_sync(0xffffffffu, s1, o);
    }
    __shared__ float r0[4], r1[4];
    const int w = tid >> 5, l = tid & 31;
    if (l == 0) { r0[w] = s0; r1[w] = s1; }
    __syncthreads();
    if (tid == 0) {
        x[2 * b]     += DT * (r0[0] + r0[1] + r0[2] + r0[3] + b4[0]);
        x[2 * b + 1] += DT * (r1[0] + r1[1] + r1[2] + r1[3] + b4[1]);
    }
}

__global__ void copy_out_kernel(const float* __restrict__ src, float* __restrict__ dst, int n) {
    int i = blockIdx.x * blockDim.x + threadIdx.x;
    if (i < n) dst[i] = src[i];
}

// ===================== host side ============================================
extern "C" void kernel_launch(void* const* d_in, const int* in_sizes, int n_in,
                              void* d_out, int out_size)
{
    const float* state = (const float*)d_in[0];
    const float* x0    = (const float*)d_in[1];
    const float* W0    = (const float*)d_in[2];
    const float* b0    = (const float*)d_in[3];
    const float* W1    = (const float*)d_in[4];
    const float* b1    = (const float*)d_in[5];
    const float* W2    = (const float*)d_in[6];
    const float* b2    = (const float*)d_in[7];
    const float* W3    = (const float*)d_in[8];
    const float* b3    = (const float*)d_in[9];
    const float* W4    = (const float*)d_in[10];
    const float* b4    = (const float*)d_in[11];
    float* out = (float*)d_out;

    float *base0p, *tvecp, *xp;
    __nv_bfloat16 *aHi, *aLo, *bHi, *bLo, *wHi, *wLo;
    cudaGetSymbolAddress((void**)&base0p, g_base0);
    cudaGetSymbolAddress((void**)&tvecp,  g_tvec);
    cudaGetSymbolAddress((void**)&xp,     g_x);
    cudaGetSymbolAddress((void**)&aHi,    g_actA_hi);
    cudaGetSymbolAddress((void**)&aLo,    g_actA_lo);
    cudaGetSymbolAddress((void**)&bHi,    g_actB_hi);
    cudaGetSymbolAddress((void**)&bLo,    g_actB_lo);
    cudaGetSymbolAddress((void**)&wHi,    g_w_hi);
    cudaGetSymbolAddress((void**)&wLo,    g_w_lo);

    static bool attr_set = false;
    if (!attr_set) {
        cudaFuncSetAttribute(gemm_hmma, cudaFuncAttributeMaxDynamicSharedMemorySize,
                             GSMEM_TOTAL);
        attr_set = true;
    }

    // one-time prep
    cudaMemcpyAsync(xp, x0, B_ * C_ * sizeof(float), cudaMemcpyDeviceToDevice);
    dim3 tb(32, 8), tg(32, 32);
    wsplit_kernel<<<tg, tb>>>(W1, wHi + 0 * (size_t)H_ * H_, wLo + 0 * (size_t)H_ * H_);
    wsplit_kernel<<<tg, tb>>>(W2, wHi + 1 * (size_t)H_ * H_, wLo + 1 * (size_t)H_ * H_);
    wsplit_kernel<<<tg, tb>>>(W3, wHi + 2 * (size_t)H_ * H_, wLo + 2 * (size_t)H_ * H_);
    tvec_kernel<<<NSTEPS, 256>>>(W0, tvecp);
    sgemm_kernel<<<dim3(H_ / BN, B_ / BM), 256>>>(state, S_, W0, H_, b0, base0p, H_, S_);

    dim3 ggrid(H_ / GBN, B_ / GBM);  // (16, 8) = 128 CTAs
    for (int i = 0; i < NSTEPS; i++) {
        layer0_act<<<(B_ * H_) / 256, 256>>>(base0p, tvecp + i * H_,
                                             W0 + (size_t)254 * H_, W0 + (size_t)255 * H_,
                                             xp, aHi, aLo);
        gemm_hmma<<<ggrid, 256, GSMEM_TOTAL>>>(aHi, aLo,
                                               wHi + 0 * (size_t)H_ * H_, wLo + 0 * (size_t)H_ * H_,
                                               b1, bHi, bLo);
        gemm_hmma<<<ggrid, 256, GSMEM_TOTAL>>>(bHi, bLo,
                                               wHi + 1 * (size_t)H_ * H_, wLo + 1 * (size_t)H_ * H_,
                                               b2, aHi, aLo);
        gemm_hmma<<<ggrid, 256, GSMEM_TOTAL>>>(aHi, aLo,
                                               wHi + 2 * (size_t)H_ * H_, wLo + 2 * (size_t)H_ * H_,
                                               b3, bHi, bLo);
        out_euler<<<B_, 128>>>(bHi, bLo, W4, b4, xp);
    }
    copy_out_kernel<<<(B_ * C_ + 255) / 256, 256>>>(xp, out, B_ * C_);
}

// round 4
// speedup vs baseline: 2.2729x; 1.0822x over previous
#include <cuda_runtime.h>
#include <cuda_bf16.h>
#include <math.h>
#include <stdint.h>

#define B_ 1024
#define S_ 254
#define C_ 2
#define H_ 1024
#define NSTEPS 50
#define DT 0.02f

// ===================== helpers =============================================
__device__ __forceinline__ uint32_t smem_to_u32(const void* p) {
    uint32_t a;
    asm("{ .reg .u64 t; cvta.to.shared.u64 t, %1; cvt.u32.u64 %0, t; }" : "=r"(a) : "l"(p));
    return a;
}
#define CP_ASYNC16(dst, src) \
    asm volatile("cp.async.cg.shared.global [%0], [%1], 16;" :: "r"(dst), "l"(src) : "memory")
#define CP_COMMIT() asm volatile("cp.async.commit_group;" ::: "memory")
#define CP_WAIT2() asm volatile("cp.async.wait_group 2;" ::: "memory")

__device__ __forceinline__ void ldsm4(uint32_t* r, uint32_t addr) {
    asm volatile("ldmatrix.sync.aligned.m8n8.x4.shared.b16 {%0,%1,%2,%3}, [%4];"
        : "=r"(r[0]), "=r"(r[1]), "=r"(r[2]), "=r"(r[3]) : "r"(addr));
}
__device__ __forceinline__ void mma16816(float* c, const uint32_t* a, const uint32_t* b) {
    asm volatile("mma.sync.aligned.m16n8k16.row.col.f32.bf16.bf16.f32 "
        "{%0,%1,%2,%3}, {%4,%5,%6,%7}, {%8,%9}, {%0,%1,%2,%3};"
        : "+f"(c[0]), "+f"(c[1]), "+f"(c[2]), "+f"(c[3])
        : "r"(a[0]), "r"(a[1]), "r"(a[2]), "r"(a[3]), "r"(b[0]), "r"(b[1]));
}

__device__ __forceinline__ float silu_f(float v) { return v / (1.0f + __expf(-v)); }

__device__ __forceinline__ void split_pair(float v0, float v1, uint32_t& hi, uint32_t& lo) {
    __nv_bfloat16 h0 = __float2bfloat16(v0);
    __nv_bfloat16 h1 = __float2bfloat16(v1);
    __nv_bfloat16 l0 = __float2bfloat16(v0 - __bfloat162float(h0));
    __nv_bfloat16 l1 = __float2bfloat16(v1 - __bfloat162float(h1));
    hi = ((uint32_t)__bfloat16_as_ushort(h1) << 16) | (uint32_t)__bfloat16_as_ushort(h0);
    lo = ((uint32_t)__bfloat16_as_ushort(l1) << 16) | (uint32_t)__bfloat16_as_ushort(l0);
}

// ===================== scratch (device globals, no allocs) ==================
__device__ float g_base0[B_ * H_];
__device__ float g_tvec[NSTEPS * H_];
__device__ float g_x[B_ * C_];
__device__ __nv_bfloat16 g_actA_hi[B_ * H_];
__device__ __nv_bfloat16 g_actA_lo[B_ * H_];
__device__ __nv_bfloat16 g_actB_hi[B_ * H_];
__device__ __nv_bfloat16 g_actB_lo[B_ * H_];
__device__ __nv_bfloat16 g_w_hi[3][H_ * H_];  // [N,K] transposed
__device__ __nv_bfloat16 g_w_lo[3][H_ * H_];

// ===================== weight transpose + bf16 split ========================
__global__ void wsplit_kernel(const float* __restrict__ W,
                              __nv_bfloat16* __restrict__ hi,
                              __nv_bfloat16* __restrict__ lo) {
    __shared__ float t[32][33];
    const int k0 = blockIdx.y * 32, n0 = blockIdx.x * 32;
    const int tx = threadIdx.x, ty = threadIdx.y;
    for (int i = ty; i < 32; i += 8)
        t[i][tx] = W[(size_t)(k0 + i) * H_ + n0 + tx];
    __syncthreads();
    for (int i = ty; i < 32; i += 8) {
        float v = t[tx][i];
        size_t o = (size_t)(n0 + i) * H_ + k0 + tx;
        __nv_bfloat16 h = __float2bfloat16(v);
        hi[o] = h;
        lo[o] = __float2bfloat16(v - __bfloat162float(h));
    }
}

// ===================== time-embedding contribution ==========================
// grid (50, 8), 128 threads: block handles 128 j's for one step.
__global__ __launch_bounds__(128) void tvec_kernel(const float* __restrict__ W0,
                                                   float* __restrict__ tvec) {
    __shared__ float temb[64];
    const int step = blockIdx.x;
    const int tid = threadIdx.x;
    const float t = (float)step * DT;
    if (tid < 64) {
        int k = tid & 31;
        float freq = expf(-9.210340371976184f * (float)k / 31.0f);
        float ang = t * freq;
        temb[tid] = (tid < 32) ? sinf(ang) : cosf(ang);
    }
    __syncthreads();
    const int j = blockIdx.y * 128 + tid;
    float acc = 0.0f;
    #pragma unroll
    for (int k = 0; k < 64; k++)
        acc += temb[k] * W0[(size_t)(256 + k) * H_ + j];
    tvec[step * H_ + j] = acc;
}

// ===================== fp32 SGEMM for base0 (K=254, one-time) ===============
#define BM 128
#define BN 64
#define BKK 16
__global__ __launch_bounds__(256) void sgemm_kernel(
    const float* __restrict__ A, int lda,
    const float* __restrict__ Bm, int ldb,
    const float* __restrict__ bias,
    float* __restrict__ Cm, int ldc, int K)
{
    __shared__ __align__(16) float As[2][BKK][BM + 4];
    __shared__ __align__(16) float Bs[2][BKK][BN];
    const int tid = threadIdx.x;
    const int tx = tid & 15, ty = tid >> 4;
    const int row0 = blockIdx.y * BM, col0 = blockIdx.x * BN;
    const int m0 = ty * 8, n0 = tx * 4;
    const int arow = tid >> 2, akq = (tid & 3) * 4;
    const int bk = tid >> 4, bn = (tid & 15) * 4;

    float acc[8][4];
    #pragma unroll
    for (int i = 0; i < 8; i++)
        #pragma unroll
        for (int j = 0; j < 4; j++) acc[i][j] = 0.0f;
    float4 ra[2], rb;

    auto gload = [&](int kt) {
        const int kbase = kt * BKK;
        #pragma unroll
        for (int i = 0; i < 2; i++) {
            int r = arow + i * 64, k = kbase + akq;
            const float* p = A + (size_t)(row0 + r) * lda + k;
            float4 v;
            v.x = (k + 0 < K) ? p[0] : 0.0f;
            v.y = (k + 1 < K) ? p[1] : 0.0f;
            v.z = (k + 2 < K) ? p[2] : 0.0f;
            v.w = (k + 3 < K) ? p[3] : 0.0f;
            ra[i] = v;
        }
        int k = kbase + bk;
        const float* p = Bm + (size_t)k * ldb + col0 + bn;
        rb = (k < K) ? *reinterpret_cast<const float4*>(p) : make_float4(0, 0, 0, 0);
    };
    auto sstore = [&](int buf) {
        #pragma unroll
        for (int i = 0; i < 2; i++) {
            int r = arow + i * 64;
            As[buf][akq + 0][r] = ra[i].x;
            As[buf][akq + 1][r] = ra[i].y;
            As[buf][akq + 2][r] = ra[i].z;
            As[buf][akq + 3][r] = ra[i].w;
        }
        *reinterpret_cast<float4*>(&Bs[buf][bk][bn]) = rb;
    };

    const int ktiles = (K + BKK - 1) / BKK;
    gload(0); sstore(0); __syncthreads();
    for (int kt = 0; kt < ktiles; kt++) {
        const int buf = kt & 1;
        if (kt + 1 < ktiles) gload(kt + 1);
        #pragma unroll
        for (int kk = 0; kk < BKK; kk++) {
            float a[8], bv[4];
            #pragma unroll
            for (int i = 0; i < 8; i++) a[i] = As[buf][kk][m0 + i];
            #pragma unroll
            for (int j = 0; j < 4; j++) bv[j] = Bs[buf][kk][n0 + j];
            #pragma unroll
            for (int i = 0; i < 8; i++)
                #pragma unroll
                for (int j = 0; j < 4; j++)
                    acc[i][j] = fmaf(a[i], bv[j], acc[i][j]);
        }
        if (kt + 1 < ktiles) sstore(buf ^ 1);
        __syncthreads();
    }
    float bb[4];
    #pragma unroll
    for (int j = 0; j < 4; j++) bb[j] = bias[col0 + n0 + j];
    #pragma unroll
    for (int i = 0; i < 8; i++) {
        const int m = row0 + m0 + i;
        float4 o;
        o.x = acc[i][0] + bb[0]; o.y = acc[i][1] + bb[1];
        o.z = acc[i][2] + bb[2]; o.w = acc[i][3] + bb[3];
        *reinterpret_cast<float4*>(Cm + (size_t)m * ldc + col0 + n0) = o;
    }
}

// ===================== HMMA split-bf16 GEMM (ILP-restructured) ==============
#define GBM 128
#define GBN 64
#define GBK 32
#define GSTAGES 4
#define OFF_AHI 0
#define OFF_ALO 8192
#define OFF_BHI 16384
#define OFF_BLO 20480
#define STAGE_BYTES 24576
#define GSMEM_TOTAL (GSTAGES * STAGE_BYTES)

__device__ __forceinline__ uint32_t soff(int r, int ch) {
    return (uint32_t)(r * 64 + (((ch ^ (r >> 1)) & 3) << 4));
}

__global__ __launch_bounds__(256, 1) void gemm_hmma(
    const __nv_bfloat16* __restrict__ Ahi, const __nv_bfloat16* __restrict__ Alo,
    const __nv_bfloat16* __restrict__ Whi, const __nv_bfloat16* __restrict__ Wlo,
    const float* __restrict__ bias,
    __nv_bfloat16* __restrict__ outHi, __nv_bfloat16* __restrict__ outLo)
{
    extern __shared__ __align__(1024) char gs[];
    const uint32_t sbase = smem_to_u32(gs);
    const int tid = threadIdx.x;
    const int row0 = blockIdx.y * GBM;
    const int col0 = blockIdx.x * GBN;

    auto load_stage = [&](int kt) {
        const uint32_t sb = sbase + (uint32_t)(kt % GSTAGES) * STAGE_BYTES;
        const int kb = kt * GBK;
        #pragma unroll
        for (int i = 0; i < 2; i++) {
            int c = tid + i * 256;
            int r = c >> 2, ch = c & 3;
            uint32_t sw = soff(r, ch);
            CP_ASYNC16(sb + OFF_AHI + sw, Ahi + (size_t)(row0 + r) * H_ + kb + ch * 8);
            CP_ASYNC16(sb + OFF_ALO + sw, Alo + (size_t)(row0 + r) * H_ + kb + ch * 8);
        }
        {
            int r = tid >> 2, ch = tid & 3;
            uint32_t sw = soff(r, ch);
            CP_ASYNC16(sb + OFF_BHI + sw, Whi + (size_t)(col0 + r) * H_ + kb + ch * 8);
            CP_ASYNC16(sb + OFF_BLO + sw, Wlo + (size_t)(col0 + r) * H_ + kb + ch * 8);
        }
    };

    const int lane = tid & 31;
    const int wid = tid >> 5;
    const int wm = wid & 3;   // 0..3 (M)
    const int wn = wid >> 2;  // 0..1 (N)

    float acc[2][4][4];
    #pragma unroll
    for (int mi = 0; mi < 2; mi++)
        #pragma unroll
        for (int ni = 0; ni < 4; ni++)
            #pragma unroll
            for (int q = 0; q < 4; q++) acc[mi][ni][q] = 0.0f;

    const int a_r = wm * 32 + (lane & 15);
    const int a_half = lane >> 4;
    const int b_r = wn * 32 + (lane & 7) + ((lane >> 4) << 3);
    const int b_half = (lane >> 3) & 1;

    load_stage(0); CP_COMMIT();
    load_stage(1); CP_COMMIT();
    load_stage(2); CP_COMMIT();

    const int NKT = H_ / GBK;  // 32
    for (int kt = 0; kt < NKT; kt++) {
        CP_WAIT2();
        __syncthreads();

        const uint32_t sb = sbase + (uint32_t)(kt % GSTAGES) * STAGE_BYTES;

        // --- load ALL fragments for this k-tile (both ks halves) ---
        uint32_t ah[2][2][4], al[2][2][4];   // [ks][mi][4]
        uint32_t bh[2][2][4], bl[2][2][4];   // [ks][nt][4]
        #pragma unroll
        for (int ks = 0; ks < 2; ks++) {
            #pragma unroll
            for (int mi = 0; mi < 2; mi++) {
                uint32_t off = soff(a_r + mi * 16, ks * 2 + a_half);
                ldsm4(ah[ks][mi], sb + OFF_AHI + off);
                ldsm4(al[ks][mi], sb + OFF_ALO + off);
            }
            #pragma unroll
            for (int nt = 0; nt < 2; nt++) {
                uint32_t off = soff(b_r + nt * 16, ks * 2 + b_half);
                ldsm4(bh[ks][nt], sb + OFF_BHI + off);
                ldsm4(bl[ks][nt], sb + OFF_BLO + off);
            }
        }

        // prefetch next+3 stage while MMAs run
        if (kt + 3 < NKT) load_stage(kt + 3);
        CP_COMMIT();

        // --- MMAs grouped by pass: 8 independent acc chains each ---
        #pragma unroll
        for (int ks = 0; ks < 2; ks++)
            #pragma unroll
            for (int mi = 0; mi < 2; mi++)
                #pragma unroll
                for (int ni = 0; ni < 4; ni++)
                    mma16816(acc[mi][ni], ah[ks][mi], &bh[ks][ni >> 1][(ni & 1) * 2]);
        #pragma unroll
        for (int ks = 0; ks < 2; ks++)
            #pragma unroll
            for (int mi = 0; mi < 2; mi++)
                #pragma unroll
                for (int ni = 0; ni < 4; ni++)
                    mma16816(acc[mi][ni], ah[ks][mi], &bl[ks][ni >> 1][(ni & 1) * 2]);
        #pragma unroll
        for (int ks = 0; ks < 2; ks++)
            #pragma unroll
            for (int mi = 0; mi < 2; mi++)
                #pragma unroll
                for (int ni = 0; ni < 4; ni++)
                    mma16816(acc[mi][ni], al[ks][mi], &bh[ks][ni >> 1][(ni & 1) * 2]);
    }

    // epilogue: bias + silu + bf16 split
    #pragma unroll
    for (int mi = 0; mi < 2; mi++) {
        const int r0g = row0 + wm * 32 + mi * 16 + (lane >> 2);
        #pragma unroll
        for (int ni = 0; ni < 4; ni++) {
            const int cg = col0 + wn * 32 + ni * 8 + (lane & 3) * 2;
            float2 bb = *reinterpret_cast<const float2*>(bias + cg);
            float v00 = silu_f(acc[mi][ni][0] + bb.x);
            float v01 = silu_f(acc[mi][ni][1] + bb.y);
            float v10 = silu_f(acc[mi][ni][2] + bb.x);
            float v11 = silu_f(acc[mi][ni][3] + bb.y);
            uint32_t h0, l0, h1, l1;
            split_pair(v00, v01, h0, l0);
            split_pair(v10, v11, h1, l1);
            *reinterpret_cast<uint32_t*>(outHi + (size_t)r0g * H_ + cg) = h0;
            *reinterpret_cast<uint32_t*>(outLo + (size_t)r0g * H_ + cg) = l0;
            *reinterpret_cast<uint32_t*>(outHi + (size_t)(r0g + 8) * H_ + cg) = h1;
            *reinterpret_cast<uint32_t*>(outLo + (size_t)(r0g + 8) * H_ + cg) = l1;
        }
    }
}

// ===================== layer-0 fused activation (step 0 only) ===============
__global__ __launch_bounds__(256) void layer0_act(
    const float* __restrict__ base0, const float* __restrict__ tvec_step,
    const float* __restrict__ w254, const float* __restrict__ w255,
    const float* __restrict__ x,
    __nv_bfloat16* __restrict__ hi, __nv_bfloat16* __restrict__ lo)
{
    const int idx = blockIdx.x * blockDim.x + threadIdx.x;
    const int b = idx >> 10;
    const int j = idx & 1023;
    float v = base0[idx] + tvec_step[j] + x[2 * b] * w254[j] + x[2 * b + 1] * w255[j];
    float hv = silu_f(v);
    __nv_bfloat16 h = __float2bfloat16(hv);
    hi[idx] = h;
    lo[idx] = __float2bfloat16(hv - __bfloat162float(h));
}

// ===================== fused: out head + Euler + next-step layer0 ===========
__global__ __launch_bounds__(128) void step_fuse(
    const __nv_bfloat16* __restrict__ hHi, const __nv_bfloat16* __restrict__ hLo,
    const float* __restrict__ W4, const float* __restrict__ b4,
    float* __restrict__ x,
    const float* __restrict__ base0, const float* __restrict__ tvec_next,
    const float* __restrict__ w254, const float* __restrict__ w255,
    __nv_bfloat16* __restrict__ aHi, __nv_bfloat16* __restrict__ aLo)
{
    const int b = blockIdx.x;
    const int tid = threadIdx.x;
    const __nv_bfloat16* ph = hHi + (size_t)b * H_;
    const __nv_bfloat16* pl = hLo + (size_t)b * H_;
    float s0 = 0.0f, s1 = 0.0f;
    for (int j = tid; j < H_; j += 128) {
        float hv = __bfloat162float(ph[j]) + __bfloat162float(pl[j]);
        float2 w = reinterpret_cast<const float2*>(W4)[j];
        s0 = fmaf(hv, w.x, s0);
        s1 = fmaf(hv, w.y, s1);
    }
    #pragma unroll
    for (int o = 16; o > 0; o >>= 1) {
        s0 += __shfl_down_sync(0xffffffffu, s0, o);
        s1 += __shfl_down_sync(0xffffffffu, s1, o);
    }
    __shared__ float r0[4], r1[4], sx[2];
    const int w = tid >> 5, l = tid & 31;
    if (l == 0) { r0[w] = s0; r1[w] = s1; }
    __syncthreads();
    if (tid == 0) {
        float xv0 = x[2 * b]     + DT * (r0[0] + r0[1] + r0[2] + r0[3] + b4[0]);
        float xv1 = x[2 * b + 1] + DT * (r1[0] + r1[1] + r1[2] + r1[3] + b4[1]);
        x[2 * b] = xv0; x[2 * b + 1] = xv1;
        sx[0] = xv0; sx[1] = xv1;
    }
    __syncthreads();
    const float xb0 = sx[0], xb1 = sx[1];
    const float* brow = base0 + (size_t)b * H_;
    __nv_bfloat16* hiRow = aHi + (size_t)b * H_;
    __nv_bfloat16* loRow = aLo + (size_t)b * H_;
    for (int j = tid; j < H_; j += 128) {
        float v = brow[j] + tvec_next[j] + xb0 * w254[j] + xb1 * w255[j];
        float hv = silu_f(v);
        __nv_bfloat16 h = __float2bfloat16(hv);
        hiRow[j] = h;
        loRow[j] = __float2bfloat16(hv - __bfloat162float(h));
    }
}

// ===================== final out head + Euler =============================
__global__ __launch_bounds__(128) void out_euler(
    const __nv_bfloat16* __restrict__ hHi, const __nv_bfloat16* __restrict__ hLo,
    const float* __restrict__ W4, const float* __restrict__ b4, float* __restrict__ x)
{
    const int b = blockIdx.x;
    const int tid = threadIdx.x;
    const __nv_bfloat16* ph = hHi + (size_t)b * H_;
    const __nv_bfloat16* pl = hLo + (size_t)b * H_;
    float s0 = 0.0f, s1 = 0.0f;
    for (int j = tid; j < H_; j += 128) {
        float hv = __bfloat162float(ph[j]) + __bfloat162float(pl[j]);
        float2 w = reinterpret_cast<const float2*>(W4)[j];
        s0 = fmaf(hv, w.x, s0);
        s1 = fmaf(hv, w.y, s1);
    }
    #pragma unroll
    for (int o = 16; o > 0; o >>= 1) {
        s0 += __shfl_down_sync(0xffffffffu, s0, o);
        s1 += __shfl_down_sync(0xffffffffu, s1, o);
    }
    __shared__ float r0[4], r1[4];
    const int w = tid >> 5, l = tid & 31;
    if (l == 0) { r0[w] = s0; r1[w] = s1; }
    __syncthreads();
    if (tid == 0) {
        x[2 * b]     += DT * (r0[0] + r0[1] + r0[2] + r0[3] + b4[0]);
        x[2 * b + 1] += DT * (r1[0] + r1[1] + r1[2] + r1[3] + b4[1]);
    }
}

__global__ void copy_out_kernel(const float* __restrict__ src, float* __restrict__ dst, int n) {
    int i = blockIdx.x * blockDim.x + threadIdx.x;
    if (i < n) dst[i] = src[i];
}

// ===================== host side ============================================
extern "C" void kernel_launch(void* const* d_in, const int* in_sizes, int n_in,
                              void* d_out, int out_size)
{
    const float* state = (const float*)d_in[0];
    const float* x0    = (const float*)d_in[1];
    const float* W0    = (const float*)d_in[2];
    const float* b0    = (const float*)d_in[3];
    const float* W1    = (const float*)d_in[4];
    const float* b1    = (const float*)d_in[5];
    const float* W2    = (const float*)d_in[6];
    const float* b2    = (const float*)d_in[7];
    const float* W3    = (const float*)d_in[8];
    const float* b3    = (const float*)d_in[9];
    const float* W4    = (const float*)d_in[10];
    const float* b4    = (const float*)d_in[11];
    float* out = (float*)d_out;

    float *base0p, *tvecp, *xp;
    __nv_bfloat16 *aHi, *aLo, *bHi, *bLo, *wHi, *wLo;
    cudaGetSymbolAddress((void**)&base0p, g_base0);
    cudaGetSymbolAddress((void**)&tvecp,  g_tvec);
    cudaGetSymbolAddress((void**)&xp,     g_x);
    cudaGetSymbolAddress((void**)&aHi,    g_actA_hi);
    cudaGetSymbolAddress((void**)&aLo,    g_actA_lo);
    cudaGetSymbolAddress((void**)&bHi,    g_actB_hi);
    cudaGetSymbolAddress((void**)&bLo,    g_actB_lo);
    cudaGetSymbolAddress((void**)&wHi,    g_w_hi);
    cudaGetSymbolAddress((void**)&wLo,    g_w_lo);

    static bool attr_set = false;
    if (!attr_set) {
        cudaFuncSetAttribute(gemm_hmma, cudaFuncAttributeMaxDynamicSharedMemorySize,
                             GSMEM_TOTAL);
        attr_set = true;
    }

    // one-time prep
    cudaMemcpyAsync(xp, x0, B_ * C_ * sizeof(float), cudaMemcpyDeviceToDevice);
    dim3 tb(32, 8), tg(32, 32);
    wsplit_kernel<<<tg, tb>>>(W1, wHi + 0 * (size_t)H_ * H_, wLo + 0 * (size_t)H_ * H_);
    wsplit_kernel<<<tg, tb>>>(W2, wHi + 1 * (size_t)H_ * H_, wLo + 1 * (size_t)H_ * H_);
    wsplit_kernel<<<tg, tb>>>(W3, wHi + 2 * (size_t)H_ * H_, wLo + 2 * (size_t)H_ * H_);
    tvec_kernel<<<dim3(NSTEPS, 8), 128>>>(W0, tvecp);
    sgemm_kernel<<<dim3(H_ / BN, B_ / BM), 256>>>(state, S_, W0, H_, b0, base0p, H_, S_);

    const float* w254 = W0 + (size_t)254 * H_;
    const float* w255 = W0 + (size_t)255 * H_;

    dim3 ggrid(H_ / GBN, B_ / GBM);  // (16, 8) = 128 CTAs
    layer0_act<<<(B_ * H_) / 256, 256>>>(base0p, tvecp, w254, w255, xp, aHi, aLo);
    for (int i = 0; i < NSTEPS; i++) {
        gemm_hmma<<<ggrid, 256, GSMEM_TOTAL>>>(aHi, aLo,
                                               wHi + 0 * (size_t)H_ * H_, wLo + 0 * (size_t)H_ * H_,
                                               b1, bHi, bLo);
        gemm_hmma<<<ggrid, 256, GSMEM_TOTAL>>>(bHi, bLo,
                                               wHi + 1 * (size_t)H_ * H_, wLo + 1 * (size_t)H_ * H_,
                                               b2, aHi, aLo);
        gemm_hmma<<<ggrid, 256, GSMEM_TOTAL>>>(aHi, aLo,
                                               wHi + 2 * (size_t)H_ * H_, wLo + 2 * (size_t)H_ * H_,
                                               b3, bHi, bLo);
        if (i + 1 < NSTEPS) {
            step_fuse<<<B_, 128>>>(bHi, bLo, W4, b4, xp, base0p,
                                   tvecp + (i + 1) * H_, w254, w255, aHi, aLo);
        } else {
            out_euler<<<B_, 128>>>(bHi, bLo, W4, b4, xp);
        }
    }
    copy_out_kernel<<<(B_ * C_ + 255) / 256, 256>>>(xp, out, B_ * C_);
}

// round 5
// speedup vs baseline: 4.2938x; 1.8891x over previous
#include <cuda_runtime.h>
#include <cuda_bf16.h>
#include <cuda_fp16.h>
#include <math.h>
#include <stdint.h>

#define B_ 1024
#define S_ 254
#define C_ 2
#define H_ 1024
#define NSTEPS 50
#define DT 0.02f

// ===================== helpers =============================================
__device__ __forceinline__ uint32_t smem_to_u32(const void* p) {
    uint32_t a;
    asm("{ .reg .u64 t; cvta.to.shared.u64 t, %1; cvt.u32.u64 %0, t; }" : "=r"(a) : "l"(p));
    return a;
}
#define CP_ASYNC16(dst, src) \
    asm volatile("cp.async.cg.shared.global [%0], [%1], 16;" :: "r"(dst), "l"(src) : "memory")
#define CP_COMMIT() asm volatile("cp.async.commit_group;" ::: "memory")
#define CP_WAIT2() asm volatile("cp.async.wait_group 2;" ::: "memory")

__device__ __forceinline__ void ldsm4(uint32_t* r, uint32_t addr) {
    asm volatile("ldmatrix.sync.aligned.m8n8.x4.shared.b16 {%0,%1,%2,%3}, [%4];"
        : "=r"(r[0]), "=r"(r[1]), "=r"(r[2]), "=r"(r[3]) : "r"(addr));
}
// fp16 MMA, fp32 accumulate
__device__ __forceinline__ void mma16816h(float* c, const uint32_t* a, const uint32_t* b) {
    asm volatile("mma.sync.aligned.m16n8k16.row.col.f32.f16.f16.f32 "
        "{%0,%1,%2,%3}, {%4,%5,%6,%7}, {%8,%9}, {%0,%1,%2,%3};"
        : "+f"(c[0]), "+f"(c[1]), "+f"(c[2]), "+f"(c[3])
        : "r"(a[0]), "r"(a[1]), "r"(a[2]), "r"(a[3]), "r"(b[0]), "r"(b[1]));
}

__device__ __forceinline__ float silu_f(float v) { return v / (1.0f + __expf(-v)); }

// ===================== scratch (device globals, no allocs) ==================
__device__ float g_base0[B_ * H_];
__device__ float g_tvec[NSTEPS * H_];
__device__ float g_x[B_ * C_];
__device__ __half g_actA[B_ * H_];
__device__ __half g_actB[B_ * H_];
__device__ __half g_w16[3][H_ * H_];   // fp16 [N,K] transposed

// ===================== weight transpose to fp16 =============================
__global__ void wconv_kernel(const float* __restrict__ W, __half* __restrict__ w16) {
    __shared__ float t[32][33];
    const int k0 = blockIdx.y * 32, n0 = blockIdx.x * 32;
    const int tx = threadIdx.x, ty = threadIdx.y;
    for (int i = ty; i < 32; i += 8)
        t[i][tx] = W[(size_t)(k0 + i) * H_ + n0 + tx];
    __syncthreads();
    for (int i = ty; i < 32; i += 8)
        w16[(size_t)(n0 + i) * H_ + k0 + tx] = __float2half_rn(t[tx][i]);
}

// ===================== time-embedding contribution ==========================
__global__ __launch_bounds__(128) void tvec_kernel(const float* __restrict__ W0,
                                                   float* __restrict__ tvec) {
    __shared__ float temb[64];
    const int step = blockIdx.x;
    const int tid = threadIdx.x;
    const float t = (float)step * DT;
    if (tid < 64) {
        int k = tid & 31;
        float freq = expf(-9.210340371976184f * (float)k / 31.0f);
        float ang = t * freq;
        temb[tid] = (tid < 32) ? sinf(ang) : cosf(ang);
    }
    __syncthreads();
    const int j = blockIdx.y * 128 + tid;
    float acc = 0.0f;
    #pragma unroll
    for (int k = 0; k < 64; k++)
        acc += temb[k] * W0[(size_t)(256 + k) * H_ + j];
    tvec[step * H_ + j] = acc;
}

// ===================== fp32 SGEMM for base0 (K=254, one-time) ===============
#define BM 128
#define BN 64
#define BKK 16
__global__ __launch_bounds__(256) void sgemm_kernel(
    const float* __restrict__ A, int lda,
    const float* __restrict__ Bm, int ldb,
    const float* __restrict__ bias,
    float* __restrict__ Cm, int ldc, int K)
{
    __shared__ __align__(16) float As[2][BKK][BM + 4];
    __shared__ __align__(16) float Bs[2][BKK][BN];
    const int tid = threadIdx.x;
    const int tx = tid & 15, ty = tid >> 4;
    const int row0 = blockIdx.y * BM, col0 = blockIdx.x * BN;
    const int m0 = ty * 8, n0 = tx * 4;
    const int arow = tid >> 2, akq = (tid & 3) * 4;
    const int bk = tid >> 4, bn = (tid & 15) * 4;

    float acc[8][4];
    #pragma unroll
    for (int i = 0; i < 8; i++)
        #pragma unroll
        for (int j = 0; j < 4; j++) acc[i][j] = 0.0f;
    float4 ra[2], rb;

    auto gload = [&](int kt) {
        const int kbase = kt * BKK;
        #pragma unroll
        for (int i = 0; i < 2; i++) {
            int r = arow + i * 64, k = kbase + akq;
            const float* p = A + (size_t)(row0 + r) * lda + k;
            float4 v;
            v.x = (k + 0 < K) ? p[0] : 0.0f;
            v.y = (k + 1 < K) ? p[1] : 0.0f;
            v.z = (k + 2 < K) ? p[2] : 0.0f;
            v.w = (k + 3 < K) ? p[3] : 0.0f;
            ra[i] = v;
        }
        int k = kbase + bk;
        const float* p = Bm + (size_t)k * ldb + col0 + bn;
        rb = (k < K) ? *reinterpret_cast<const float4*>(p) : make_float4(0, 0, 0, 0);
    };
    auto sstore = [&](int buf) {
        #pragma unroll
        for (int i = 0; i < 2; i++) {
            int r = arow + i * 64;
            As[buf][akq + 0][r] = ra[i].x;
            As[buf][akq + 1][r] = ra[i].y;
            As[buf][akq + 2][r] = ra[i].z;
            As[buf][akq + 3][r] = ra[i].w;
        }
        *reinterpret_cast<float4*>(&Bs[buf][bk][bn]) = rb;
    };

    const int ktiles = (K + BKK - 1) / BKK;
    gload(0); sstore(0); __syncthreads();
    for (int kt = 0; kt < ktiles; kt++) {
        const int buf = kt & 1;
        if (kt + 1 < ktiles) gload(kt + 1);
        #pragma unroll
        for (int kk = 0; kk < BKK; kk++) {
            float a[8], bv[4];
            #pragma unroll
            for (int i = 0; i < 8; i++) a[i] = As[buf][kk][m0 + i];
            #pragma unroll
            for (int j = 0; j < 4; j++) bv[j] = Bs[buf][kk][n0 + j];
            #pragma unroll
            for (int i = 0; i < 8; i++)
                #pragma unroll
                for (int j = 0; j < 4; j++)
                    acc[i][j] = fmaf(a[i], bv[j], acc[i][j]);
        }
        if (kt + 1 < ktiles) sstore(buf ^ 1);
        __syncthreads();
    }
    float bb[4];
    #pragma unroll
    for (int j = 0; j < 4; j++) bb[j] = bias[col0 + n0 + j];
    #pragma unroll
    for (int i = 0; i < 8; i++) {
        const int m = row0 + m0 + i;
        float4 o;
        o.x = acc[i][0] + bb[0]; o.y = acc[i][1] + bb[1];
        o.z = acc[i][2] + bb[2]; o.w = acc[i][3] + bb[3];
        *reinterpret_cast<float4*>(Cm + (size_t)m * ldc + col0 + n0) = o;
    }
}

// ===================== single-pass fp16 HMMA GEMM ===========================
// C[b,n] = silu(A[b,:]·W[n,:] + bias[n]) stored fp16.
// A: [M,K] fp16; W: [N,K] fp16. BM=128, BN=64, BK=32, 4-stage cp.async.
#define GBM 128
#define GBN 64
#define GBK 32
#define GSTAGES 4
#define OFF_A 0
#define OFF_B 8192
#define STAGE_BYTES 12288
#define GSMEM_TOTAL (GSTAGES * STAGE_BYTES)

__device__ __forceinline__ uint32_t soff(int r, int ch) {
    return (uint32_t)(r * 64 + (((ch ^ (r >> 1)) & 3) << 4));
}

__global__ __launch_bounds__(256, 1) void gemm_hmma(
    const __half* __restrict__ A, const __half* __restrict__ W,
    const float* __restrict__ bias, __half* __restrict__ outC)
{
    extern __shared__ __align__(1024) char gs[];
    const uint32_t sbase = smem_to_u32(gs);
    const int tid = threadIdx.x;
    const int row0 = blockIdx.y * GBM;
    const int col0 = blockIdx.x * GBN;

    auto load_stage = [&](int kt) {
        const uint32_t sb = sbase + (uint32_t)(kt % GSTAGES) * STAGE_BYTES;
        const int kb = kt * GBK;
        #pragma unroll
        for (int i = 0; i < 2; i++) {
            int c = tid + i * 256;
            int r = c >> 2, ch = c & 3;
            CP_ASYNC16(sb + OFF_A + soff(r, ch), A + (size_t)(row0 + r) * H_ + kb + ch * 8);
        }
        {
            int r = tid >> 2, ch = tid & 3;
            CP_ASYNC16(sb + OFF_B + soff(r, ch), W + (size_t)(col0 + r) * H_ + kb + ch * 8);
        }
    };

    const int lane = tid & 31;
    const int wid = tid >> 5;
    const int wm = wid & 3;   // 0..3 (M)
    const int wn = wid >> 2;  // 0..1 (N)

    float acc[2][4][4];
    #pragma unroll
    for (int mi = 0; mi < 2; mi++)
        #pragma unroll
        for (int ni = 0; ni < 4; ni++)
            #pragma unroll
            for (int q = 0; q < 4; q++) acc[mi][ni][q] = 0.0f;

    const int a_r = wm * 32 + (lane & 15);
    const int a_half = lane >> 4;
    const int b_r = wn * 32 + (lane & 7) + ((lane >> 4) << 3);
    const int b_half = (lane >> 3) & 1;

    load_stage(0); CP_COMMIT();
    load_stage(1); CP_COMMIT();
    load_stage(2); CP_COMMIT();

    const int NKT = H_ / GBK;  // 32
    for (int kt = 0; kt < NKT; kt++) {
        CP_WAIT2();
        __syncthreads();

        const uint32_t sb = sbase + (uint32_t)(kt % GSTAGES) * STAGE_BYTES;

        uint32_t af[2][2][4];   // [ks][mi][4]
        uint32_t bf[2][2][4];   // [ks][nt][4]
        #pragma unroll
        for (int ks = 0; ks < 2; ks++) {
            #pragma unroll
            for (int mi = 0; mi < 2; mi++)
                ldsm4(af[ks][mi], sb + OFF_A + soff(a_r + mi * 16, ks * 2 + a_half));
            #pragma unroll
            for (int nt = 0; nt < 2; nt++)
                ldsm4(bf[ks][nt], sb + OFF_B + soff(b_r + nt * 16, ks * 2 + b_half));
        }

        if (kt + 3 < NKT) load_stage(kt + 3);
        CP_COMMIT();

        #pragma unroll
        for (int ks = 0; ks < 2; ks++)
            #pragma unroll
            for (int mi = 0; mi < 2; mi++)
                #pragma unroll
                for (int ni = 0; ni < 4; ni++)
                    mma16816h(acc[mi][ni], af[ks][mi], &bf[ks][ni >> 1][(ni & 1) * 2]);
    }

    // epilogue: bias + silu, packed half2 stores
    #pragma unroll
    for (int mi = 0; mi < 2; mi++) {
        const int r0g = row0 + wm * 32 + mi * 16 + (lane >> 2);
        #pragma unroll
        for (int ni = 0; ni < 4; ni++) {
            const int cg = col0 + wn * 32 + ni * 8 + (lane & 3) * 2;
            float2 bb = *reinterpret_cast<const float2*>(bias + cg);
            __half2 p0 = __floats2half2_rn(silu_f(acc[mi][ni][0] + bb.x),
                                           silu_f(acc[mi][ni][1] + bb.y));
            __half2 p1 = __floats2half2_rn(silu_f(acc[mi][ni][2] + bb.x),
                                           silu_f(acc[mi][ni][3] + bb.y));
            *reinterpret_cast<__half2*>(outC + (size_t)r0g * H_ + cg) = p0;
            *reinterpret_cast<__half2*>(outC + (size_t)(r0g + 8) * H_ + cg) = p1;
        }
    }
}

// ===================== layer-0 fused activation (step 0 only) ===============
__global__ __launch_bounds__(256) void layer0_act(
    const float* __restrict__ base0, const float* __restrict__ tvec_step,
    const float* __restrict__ w254, const float* __restrict__ w255,
    const float* __restrict__ x, __half* __restrict__ h)
{
    const int idx = blockIdx.x * blockDim.x + threadIdx.x;
    const int b = idx >> 10;
    const int j = idx & 1023;
    float v = base0[idx] + tvec_step[j] + x[2 * b] * w254[j] + x[2 * b + 1] * w255[j];
    h[idx] = __float2half_rn(silu_f(v));
}

// ===================== fused: out head + Euler + next-step layer0 ===========
__global__ __launch_bounds__(128) void step_fuse(
    const __half* __restrict__ hIn,
    const float* __restrict__ W4, const float* __restrict__ b4,
    float* __restrict__ x,
    const float* __restrict__ base0, const float* __restrict__ tvec_next,
    const float* __restrict__ w254, const float* __restrict__ w255,
    __half* __restrict__ hOut)
{
    const int b = blockIdx.x;
    const int tid = threadIdx.x;
    const __half* ph = hIn + (size_t)b * H_;
    float s0 = 0.0f, s1 = 0.0f;
    for (int j = tid; j < H_; j += 128) {
        float hv = __half2float(ph[j]);
        float2 w = reinterpret_cast<const float2*>(W4)[j];
        s0 = fmaf(hv, w.x, s0);
        s1 = fmaf(hv, w.y, s1);
    }
    #pragma unroll
    for (int o = 16; o > 0; o >>= 1) {
        s0 += __shfl_down_sync(0xffffffffu, s0, o);
        s1 += __shfl_down_sync(0xffffffffu, s1, o);
    }
    __shared__ float r0[4], r1[4], sx[2];
    const int w = tid >> 5, l = tid & 31;
    if (l == 0) { r0[w] = s0; r1[w] = s1; }
    __syncthreads();
    if (tid == 0) {
        float xv0 = x[2 * b]     + DT * (r0[0] + r0[1] + r0[2] + r0[3] + b4[0]);
        float xv1 = x[2 * b + 1] + DT * (r1[0] + r1[1] + r1[2] + r1[3] + b4[1]);
        x[2 * b] = xv0; x[2 * b + 1] = xv1;
        sx[0] = xv0; sx[1] = xv1;
    }
    __syncthreads();
    const float xb0 = sx[0], xb1 = sx[1];
    const float* brow = base0 + (size_t)b * H_;
    __half* orow = hOut + (size_t)b * H_;
    for (int j = tid; j < H_; j += 128) {
        float v = brow[j] + tvec_next[j] + xb0 * w254[j] + xb1 * w255[j];
        orow[j] = __float2half_rn(silu_f(v));
    }
}

// ===================== final out head + Euler ===============================
__global__ __launch_bounds__(128) void out_euler(
    const __half* __restrict__ hIn,
    const float* __restrict__ W4, const float* __restrict__ b4, float* __restrict__ x)
{
    const int b = blockIdx.x;
    const int tid = threadIdx.x;
    const __half* ph = hIn + (size_t)b * H_;
    float s0 = 0.0f, s1 = 0.0f;
    for (int j = tid; j < H_; j += 128) {
        float hv = __half2float(ph[j]);
        float2 w = reinterpret_cast<const float2*>(W4)[j];
        s0 = fmaf(hv, w.x, s0);
        s1 = fmaf(hv, w.y, s1);
    }
    #pragma unroll
    for (int o = 16; o > 0; o >>= 1) {
        s0 += __shfl_down_sync(0xffffffffu, s0, o);
        s1 += __shfl_down_sync(0xffffffffu, s1, o);
    }
    __shared__ float r0[4], r1[4];
    const int w = tid >> 5, l = tid & 31;
    if (l == 0) { r0[w] = s0; r1[w] = s1; }
    __syncthreads();
    if (tid == 0) {
        x[2 * b]     += DT * (r0[0] + r0[1] + r0[2] + r0[3] + b4[0]);
        x[2 * b + 1] += DT * (r1[0] + r1[1] + r1[2] + r1[3] + b4[1]);
    }
}

__global__ void copy_out_kernel(const float* __restrict__ src, float* __restrict__ dst, int n) {
    int i = blockIdx.x * blockDim.x + threadIdx.x;
    if (i < n) dst[i] = src[i];
}

// ===================== host side ============================================
extern "C" void kernel_launch(void* const* d_in, const int* in_sizes, int n_in,
                              void* d_out, int out_size)
{
    const float* state = (const float*)d_in[0];
    const float* x0    = (const float*)d_in[1];
    const float* W0    = (const float*)d_in[2];
    const float* b0    = (const float*)d_in[3];
    const float* W1    = (const float*)d_in[4];
    const float* b1    = (const float*)d_in[5];
    const float* W2    = (const float*)d_in[6];
    const float* b2    = (const float*)d_in[7];
    const float* W3    = (const float*)d_in[8];
    const float* b3    = (const float*)d_in[9];
    const float* W4    = (const float*)d_in[10];
    const float* b4    = (const float*)d_in[11];
    float* out = (float*)d_out;

    float *base0p, *tvecp, *xp;
    __half *actA, *actB, *w16;
    cudaGetSymbolAddress((void**)&base0p, g_base0);
    cudaGetSymbolAddress((void**)&tvecp,  g_tvec);
    cudaGetSymbolAddress((void**)&xp,     g_x);
    cudaGetSymbolAddress((void**)&actA,   g_actA);
    cudaGetSymbolAddress((void**)&actB,   g_actB);
    cudaGetSymbolAddress((void**)&w16,    g_w16);

    static bool attr_set = false;
    if (!attr_set) {
        cudaFuncSetAttribute(gemm_hmma, cudaFuncAttributeMaxDynamicSharedMemorySize,
                             GSMEM_TOTAL);
        attr_set = true;
    }

    // one-time prep
    cudaMemcpyAsync(xp, x0, B_ * C_ * sizeof(float), cudaMemcpyDeviceToDevice);
    dim3 tb(32, 8), tg(32, 32);
    wconv_kernel<<<tg, tb>>>(W1, w16 + 0 * (size_t)H_ * H_);
    wconv_kernel<<<tg, tb>>>(W2, w16 + 1 * (size_t)H_ * H_);
    wconv_kernel<<<tg, tb>>>(W3, w16 + 2 * (size_t)H_ * H_);
    tvec_kernel<<<dim3(NSTEPS, 8), 128>>>(W0, tvecp);
    sgemm_kernel<<<dim3(H_ / BN, B_ / BM), 256>>>(state, S_, W0, H_, b0, base0p, H_, S_);

    const float* w254 = W0 + (size_t)254 * H_;
    const float* w255 = W0 + (size_t)255 * H_;

    dim3 ggrid(H_ / GBN, B_ / GBM);  // (16, 8) = 128 CTAs
    layer0_act<<<(B_ * H_) / 256, 256>>>(base0p, tvecp, w254, w255, xp, actA);
    for (int i = 0; i < NSTEPS; i++) {
        gemm_hmma<<<ggrid, 256, GSMEM_TOTAL>>>(actA, w16 + 0 * (size_t)H_ * H_, b1, actB);
        gemm_hmma<<<ggrid, 256, GSMEM_TOTAL>>>(actB, w16 + 1 * (size_t)H_ * H_, b2, actA);
        gemm_hmma<<<ggrid, 256, GSMEM_TOTAL>>>(actA, w16 + 2 * (size_t)H_ * H_, b3, actB);
        if (i + 1 < NSTEPS) {
            step_fuse<<<B_, 128>>>(actB, W4, b4, xp, base0p,
                                   tvecp + (i + 1) * H_, w254, w255, actA);
        } else {
            out_euler<<<B_, 128>>>(actB, W4, b4, xp);
        }
    }
    copy_out_kernel<<<(B_ * C_ + 255) / 256, 256>>>(xp, out, B_ * C_);
}